// round 5
// baseline (speedup 1.0000x reference)
#include <cuda_runtime.h>

#define BATCH 4
#define CCH   256
#define HWN   4096
#define NGRP  8
#define CPG   32          // channels per group
#define NHEAD 4
#define HDIM  64
#define QKVC  768

// ---------------- scratch (device globals; no runtime allocation) ------------
__device__ float g_H  [BATCH * HWN * CCH];    // normalized input, [b][p][c]
__device__ float g_QKV[BATCH * HWN * QKVC];   // [b][p][o]  o: 0..255 Q, 256..511 K, 512..767 V
__device__ float g_AO [BATCH * HWN * CCH];    // attention output, [b][p][c]
__device__ float g_mean[BATCH * NGRP];
__device__ float g_rstd[BATCH * NGRP];

// ---------------- 1) GroupNorm statistics -----------------------------------
// one block per (b,g); group data is a contiguous 32*4096-float run
__global__ void gn_stats(const float* __restrict__ x) {
    int bg = blockIdx.x;
    const float* p = x + (size_t)bg * CPG * HWN;
    const int N = CPG * HWN;
    float s = 0.f, sq = 0.f;
    for (int i = threadIdx.x; i < N; i += blockDim.x) {
        float v = p[i];
        s += v; sq += v * v;
    }
    __shared__ float ss[32], sqs[32];
    #pragma unroll
    for (int o = 16; o; o >>= 1) {
        s  += __shfl_down_sync(0xffffffffu, s, o);
        sq += __shfl_down_sync(0xffffffffu, sq, o);
    }
    int w = threadIdx.x >> 5, l = threadIdx.x & 31;
    if (l == 0) { ss[w] = s; sqs[w] = sq; }
    __syncthreads();
    if (w == 0) {
        int nw = blockDim.x >> 5;
        s  = (l < nw) ? ss[l]  : 0.f;
        sq = (l < nw) ? sqs[l] : 0.f;
        #pragma unroll
        for (int o = 16; o; o >>= 1) {
            s  += __shfl_down_sync(0xffffffffu, s, o);
            sq += __shfl_down_sync(0xffffffffu, sq, o);
        }
        if (l == 0) {
            float m = s / (float)N;
            float v = sq / (float)N - m * m;
            g_mean[bg] = m;
            g_rstd[bg] = rsqrtf(v + 1e-5f);
        }
    }
}

// ---------------- 2) normalize + transpose [b,c,p] -> [b,p,c] ----------------
__global__ void gn_norm_t(const float* __restrict__ x,
                          const float* __restrict__ gamma,
                          const float* __restrict__ beta) {
    __shared__ float tile[32][33];
    int b  = blockIdx.z;
    int c0 = blockIdx.y * 32;
    int p0 = blockIdx.x * 32;
    int tx = threadIdx.x, ty = threadIdx.y;
    #pragma unroll
    for (int i = 0; i < 4; i++) {
        int c  = c0 + ty + 8 * i;
        int bg = b * NGRP + (c >> 5);
        float v = x[((size_t)(b * CCH + c)) * HWN + p0 + tx];
        tile[ty + 8 * i][tx] = (v - g_mean[bg]) * g_rstd[bg] * gamma[c] + beta[c];
    }
    __syncthreads();
    #pragma unroll
    for (int i = 0; i < 4; i++) {
        int p = p0 + ty + 8 * i;
        g_H[((size_t)(b * HWN + p)) * CCH + c0 + tx] = tile[tx][ty + 8 * i];
    }
}

// ---------------- 3) QKV GEMM: out[b][p][o] = sum_c H[b][p][c]*W[o][c] + bias[o]
__global__ void __launch_bounds__(256) qkv_gemm(const float* __restrict__ W,
                                                const float* __restrict__ bias) {
    __shared__ float Hs[64][33];
    __shared__ float Ws[64][33];
    int b  = blockIdx.z;
    int o0 = blockIdx.y * 64;
    int p0 = blockIdx.x * 64;
    int t  = threadIdx.x, tx = t & 15, ty = t >> 4;

    const float* Hb = g_H + (size_t)(b * HWN + p0) * CCH;
    float acc[4][4];
    #pragma unroll
    for (int r = 0; r < 4; r++)
        #pragma unroll
        for (int c = 0; c < 4; c++) acc[r][c] = 0.f;

    for (int k0 = 0; k0 < CCH; k0 += 32) {
        __syncthreads();
        #pragma unroll
        for (int it = 0; it < 2; it++) {
            int lin = t + 256 * it;
            int row = lin >> 3, cg = lin & 7;
            float4 hv = *(const float4*)&Hb[(size_t)row * CCH + k0 + 4 * cg];
            Hs[row][4 * cg + 0] = hv.x; Hs[row][4 * cg + 1] = hv.y;
            Hs[row][4 * cg + 2] = hv.z; Hs[row][4 * cg + 3] = hv.w;
            float4 wv = *(const float4*)&W[(size_t)(o0 + row) * CCH + k0 + 4 * cg];
            Ws[row][4 * cg + 0] = wv.x; Ws[row][4 * cg + 1] = wv.y;
            Ws[row][4 * cg + 2] = wv.z; Ws[row][4 * cg + 3] = wv.w;
        }
        __syncthreads();
        #pragma unroll 16
        for (int k = 0; k < 32; k++) {
            float a[4], w[4];
            #pragma unroll
            for (int r = 0; r < 4; r++) a[r] = Hs[4 * ty + r][k];
            #pragma unroll
            for (int c = 0; c < 4; c++) w[c] = Ws[4 * tx + c][k];
            #pragma unroll
            for (int r = 0; r < 4; r++)
                #pragma unroll
                for (int c = 0; c < 4; c++) acc[r][c] += a[r] * w[c];
        }
    }
    float4 bs = *(const float4*)&bias[o0 + 4 * tx];
    float* Ob = g_QKV + (size_t)b * HWN * QKVC;
    #pragma unroll
    for (int r = 0; r < 4; r++) {
        float4 o4 = make_float4(acc[r][0] + bs.x, acc[r][1] + bs.y,
                                acc[r][2] + bs.z, acc[r][3] + bs.w);
        *(float4*)&Ob[(size_t)(p0 + 4 * ty + r) * QKVC + o0 + 4 * tx] = o4;
    }
}

// ---------------- 4) flash attention, BM=BN=64, fp32 -------------------------
__global__ void __launch_bounds__(256) attn_flash() {
    extern __shared__ float sm[];
    float (*Qs)[65] = (float(*)[65])(sm);
    float (*Ks)[65] = (float(*)[65])(sm + 64 * 65);
    float (*Vs)[65] = (float(*)[65])(sm + 2 * 64 * 65);
    float (*Ps)[65] = (float(*)[65])(sm + 3 * 64 * 65);

    int b = blockIdx.z, h = blockIdx.y, q0 = blockIdx.x * 64;
    int t = threadIdx.x, tx = t & 15, ty = t >> 4;
    const float* base = g_QKV + (size_t)b * HWN * QKVC + h * HDIM;

    // load Q tile (64 x 64)
    #pragma unroll
    for (int it = 0; it < 4; it++) {
        int lin = t + 256 * it;
        int row = lin >> 4, dg = lin & 15;
        float4 v = *(const float4*)&base[(size_t)(q0 + row) * QKVC + 4 * dg];
        Qs[row][4 * dg + 0] = v.x; Qs[row][4 * dg + 1] = v.y;
        Qs[row][4 * dg + 2] = v.z; Qs[row][4 * dg + 3] = v.w;
    }

    float acco[4][4];
    float mrun[4], lrun[4];
    #pragma unroll
    for (int r = 0; r < 4; r++) {
        mrun[r] = -1e30f; lrun[r] = 0.f;
        #pragma unroll
        for (int c = 0; c < 4; c++) acco[r][c] = 0.f;
    }

    const float scale = 0.125f;   // 1/sqrt(64)

    for (int j0 = 0; j0 < HWN; j0 += 64) {
        __syncthreads();   // previous PV done before K/V/P overwrite
        #pragma unroll
        for (int it = 0; it < 4; it++) {
            int lin = t + 256 * it;
            int row = lin >> 4, dg = lin & 15;
            float4 kv = *(const float4*)&base[(size_t)(j0 + row) * QKVC + 256 + 4 * dg];
            Ks[row][4 * dg + 0] = kv.x; Ks[row][4 * dg + 1] = kv.y;
            Ks[row][4 * dg + 2] = kv.z; Ks[row][4 * dg + 3] = kv.w;
            float4 vv = *(const float4*)&base[(size_t)(j0 + row) * QKVC + 512 + 4 * dg];
            Vs[row][4 * dg + 0] = vv.x; Vs[row][4 * dg + 1] = vv.y;
            Vs[row][4 * dg + 2] = vv.z; Vs[row][4 * dg + 3] = vv.w;
        }
        __syncthreads();

        // S = Q K^T  (4x4 per thread)
        float s[4][4];
        #pragma unroll
        for (int r = 0; r < 4; r++)
            #pragma unroll
            for (int c = 0; c < 4; c++) s[r][c] = 0.f;
        #pragma unroll 8
        for (int d = 0; d < 64; d++) {
            float qa[4], kb[4];
            #pragma unroll
            for (int r = 0; r < 4; r++) qa[r] = Qs[4 * ty + r][d];
            #pragma unroll
            for (int c = 0; c < 4; c++) kb[c] = Ks[4 * tx + c][d];
            #pragma unroll
            for (int r = 0; r < 4; r++)
                #pragma unroll
                for (int c = 0; c < 4; c++) s[r][c] += qa[r] * kb[c];
        }

        // online softmax per owned row
        #pragma unroll
        for (int r = 0; r < 4; r++) {
            float mx = s[r][0];
            #pragma unroll
            for (int c = 1; c < 4; c++) mx = fmaxf(mx, s[r][c]);
            mx *= scale;
            #pragma unroll
            for (int o = 1; o < 16; o <<= 1)
                mx = fmaxf(mx, __shfl_xor_sync(0xffffffffu, mx, o));
            float mnew = fmaxf(mrun[r], mx);
            float alpha = __expf(mrun[r] - mnew);
            float rs = 0.f;
            #pragma unroll
            for (int c = 0; c < 4; c++) {
                float pv = __expf(s[r][c] * scale - mnew);
                Ps[4 * ty + r][4 * tx + c] = pv;
                rs += pv;
            }
            #pragma unroll
            for (int o = 1; o < 16; o <<= 1)
                rs += __shfl_xor_sync(0xffffffffu, rs, o);
            lrun[r] = lrun[r] * alpha + rs;
            mrun[r] = mnew;
            #pragma unroll
            for (int c = 0; c < 4; c++) acco[r][c] *= alpha;
        }
        __syncthreads();

        // O += P V
        #pragma unroll 8
        for (int j = 0; j < 64; j++) {
            float pa[4], vb[4];
            #pragma unroll
            for (int r = 0; r < 4; r++) pa[r] = Ps[4 * ty + r][j];
            #pragma unroll
            for (int c = 0; c < 4; c++) vb[c] = Vs[j][4 * tx + c];
            #pragma unroll
            for (int r = 0; r < 4; r++)
                #pragma unroll
                for (int c = 0; c < 4; c++) acco[r][c] += pa[r] * vb[c];
        }
    }

    float* AO = g_AO + (size_t)b * HWN * CCH + h * HDIM;
    #pragma unroll
    for (int r = 0; r < 4; r++) {
        float inv = 1.f / lrun[r];
        float4 o4 = make_float4(acco[r][0] * inv, acco[r][1] * inv,
                                acco[r][2] * inv, acco[r][3] * inv);
        *(float4*)&AO[(size_t)(q0 + 4 * ty + r) * CCH + 4 * tx] = o4;
    }
}

// ---------------- 5) proj GEMM + bias + residual -----------------------------
// out[b][o][p] = x[b][o][p] + bias[o] + sum_c AO[b][p][c] * Wp[o][c]
__global__ void __launch_bounds__(256) proj_res(const float* __restrict__ x,
                                                const float* __restrict__ W,
                                                const float* __restrict__ bias,
                                                float* __restrict__ out) {
    __shared__ float Ws[64][33];
    __shared__ float As[64][33];
    int b  = blockIdx.z;
    int o0 = blockIdx.y * 64;
    int p0 = blockIdx.x * 64;
    int t  = threadIdx.x, tx = t & 15, ty = t >> 4;

    const float* Ab = g_AO + (size_t)(b * HWN + p0) * CCH;
    float acc[4][4];
    #pragma unroll
    for (int r = 0; r < 4; r++)
        #pragma unroll
        for (int c = 0; c < 4; c++) acc[r][c] = 0.f;

    for (int k0 = 0; k0 < CCH; k0 += 32) {
        __syncthreads();
        #pragma unroll
        for (int it = 0; it < 2; it++) {
            int lin = t + 256 * it;
            int row = lin >> 3, cg = lin & 7;
            float4 wv = *(const float4*)&W[(size_t)(o0 + row) * CCH + k0 + 4 * cg];
            Ws[row][4 * cg + 0] = wv.x; Ws[row][4 * cg + 1] = wv.y;
            Ws[row][4 * cg + 2] = wv.z; Ws[row][4 * cg + 3] = wv.w;
            float4 av = *(const float4*)&Ab[(size_t)row * CCH + k0 + 4 * cg];
            As[row][4 * cg + 0] = av.x; As[row][4 * cg + 1] = av.y;
            As[row][4 * cg + 2] = av.z; As[row][4 * cg + 3] = av.w;
        }
        __syncthreads();
        #pragma unroll 16
        for (int k = 0; k < 32; k++) {
            float w[4], a[4];
            #pragma unroll
            for (int r = 0; r < 4; r++) w[r] = Ws[4 * ty + r][k];
            #pragma unroll
            for (int c = 0; c < 4; c++) a[c] = As[4 * tx + c][k];
            #pragma unroll
            for (int r = 0; r < 4; r++)
                #pragma unroll
                for (int c = 0; c < 4; c++) acc[r][c] += w[r] * a[c];
        }
    }
    #pragma unroll
    for (int r = 0; r < 4; r++) {
        int o = o0 + 4 * ty + r;
        float bb = bias[o];
        size_t idx = ((size_t)(b * CCH + o)) * HWN + p0 + 4 * tx;
        float4 x4 = *(const float4*)&x[idx];
        float4 r4 = make_float4(x4.x + acc[r][0] + bb, x4.y + acc[r][1] + bb,
                                x4.z + acc[r][2] + bb, x4.w + acc[r][3] + bb);
        *(float4*)&out[idx] = r4;
    }
}

// ---------------- launcher ---------------------------------------------------
extern "C" void kernel_launch(void* const* d_in, const int* in_sizes, int n_in,
                              void* d_out, int out_size) {
    const float* x      = (const float*)d_in[0];
    const float* gamma  = (const float*)d_in[1];
    const float* beta   = (const float*)d_in[2];
    const float* w_qkv  = (const float*)d_in[3];
    const float* b_qkv  = (const float*)d_in[4];
    const float* w_proj = (const float*)d_in[5];
    const float* b_proj = (const float*)d_in[6];
    float* out = (float*)d_out;

    gn_stats<<<BATCH * NGRP, 1024>>>(x);
    gn_norm_t<<<dim3(HWN / 32, CCH / 32, BATCH), dim3(32, 8)>>>(x, gamma, beta);
    qkv_gemm<<<dim3(HWN / 64, QKVC / 64, BATCH), 256>>>(w_qkv, b_qkv);

    const int smem = 4 * 64 * 65 * (int)sizeof(float);   // 66,560 B
    cudaFuncSetAttribute(attn_flash, cudaFuncAttributeMaxDynamicSharedMemorySize, smem);
    attn_flash<<<dim3(HWN / 64, NHEAD, BATCH), 256, smem>>>();

    proj_res<<<dim3(HWN / 64, CCH / 64, BATCH), 256>>>(x, w_proj, b_proj, out);
}

// round 6
// speedup vs baseline: 1.0031x; 1.0031x over previous
#include <cuda_runtime.h>

#define BATCH 4
#define CCH   256
#define HWN   4096
#define NGRP  8
#define CPG   32          // channels per group
#define NHEAD 4
#define HDIM  64
#define QKVC  768

// ---------------- scratch (device globals; no runtime allocation) ------------
__device__ float g_H  [BATCH * HWN * CCH];    // normalized input, [b][p][c]
__device__ float g_QKV[BATCH * HWN * QKVC];   // [b][p][o]  o: 0..255 Q, 256..511 K, 512..767 V
__device__ float g_AO [BATCH * HWN * CCH];    // attention output, [b][p][c]
__device__ float g_mean[BATCH * NGRP];
__device__ float g_rstd[BATCH * NGRP];

// ---------------- 1) GroupNorm statistics -----------------------------------
// one block per (b,g); group data is a contiguous 32*4096-float run
__global__ void gn_stats(const float* __restrict__ x) {
    int bg = blockIdx.x;
    const float* p = x + (size_t)bg * CPG * HWN;
    const int N = CPG * HWN;
    float s = 0.f, sq = 0.f;
    for (int i = threadIdx.x; i < N; i += blockDim.x) {
        float v = p[i];
        s += v; sq += v * v;
    }
    __shared__ float ss[32], sqs[32];
    #pragma unroll
    for (int o = 16; o; o >>= 1) {
        s  += __shfl_down_sync(0xffffffffu, s, o);
        sq += __shfl_down_sync(0xffffffffu, sq, o);
    }
    int w = threadIdx.x >> 5, l = threadIdx.x & 31;
    if (l == 0) { ss[w] = s; sqs[w] = sq; }
    __syncthreads();
    if (w == 0) {
        int nw = blockDim.x >> 5;
        s  = (l < nw) ? ss[l]  : 0.f;
        sq = (l < nw) ? sqs[l] : 0.f;
        #pragma unroll
        for (int o = 16; o; o >>= 1) {
            s  += __shfl_down_sync(0xffffffffu, s, o);
            sq += __shfl_down_sync(0xffffffffu, sq, o);
        }
        if (l == 0) {
            float m = s / (float)N;
            float v = sq / (float)N - m * m;
            g_mean[bg] = m;
            g_rstd[bg] = rsqrtf(v + 1e-5f);
        }
    }
}

// ---------------- 2) normalize + transpose [b,c,p] -> [b,p,c] ----------------
__global__ void gn_norm_t(const float* __restrict__ x,
                          const float* __restrict__ gamma,
                          const float* __restrict__ beta) {
    __shared__ float tile[32][33];
    int b  = blockIdx.z;
    int c0 = blockIdx.y * 32;
    int p0 = blockIdx.x * 32;
    int tx = threadIdx.x, ty = threadIdx.y;
    #pragma unroll
    for (int i = 0; i < 4; i++) {
        int c  = c0 + ty + 8 * i;
        int bg = b * NGRP + (c >> 5);
        float v = x[((size_t)(b * CCH + c)) * HWN + p0 + tx];
        tile[ty + 8 * i][tx] = (v - g_mean[bg]) * g_rstd[bg] * gamma[c] + beta[c];
    }
    __syncthreads();
    #pragma unroll
    for (int i = 0; i < 4; i++) {
        int p = p0 + ty + 8 * i;
        g_H[((size_t)(b * HWN + p)) * CCH + c0 + tx] = tile[tx][ty + 8 * i];
    }
}

// ---------------- 3) QKV GEMM: out[b][p][o] = sum_c H[b][p][c]*W[o][c] + bias[o]
__global__ void __launch_bounds__(256) qkv_gemm(const float* __restrict__ W,
                                                const float* __restrict__ bias) {
    __shared__ float Hs[64][33];
    __shared__ float Ws[64][33];
    int b  = blockIdx.z;
    int o0 = blockIdx.y * 64;
    int p0 = blockIdx.x * 64;
    int t  = threadIdx.x, tx = t & 15, ty = t >> 4;

    const float* Hb = g_H + (size_t)(b * HWN + p0) * CCH;
    float acc[4][4];
    #pragma unroll
    for (int r = 0; r < 4; r++)
        #pragma unroll
        for (int c = 0; c < 4; c++) acc[r][c] = 0.f;

    for (int k0 = 0; k0 < CCH; k0 += 32) {
        __syncthreads();
        #pragma unroll
        for (int it = 0; it < 2; it++) {
            int lin = t + 256 * it;
            int row = lin >> 3, cg = lin & 7;
            float4 hv = *(const float4*)&Hb[(size_t)row * CCH + k0 + 4 * cg];
            Hs[row][4 * cg + 0] = hv.x; Hs[row][4 * cg + 1] = hv.y;
            Hs[row][4 * cg + 2] = hv.z; Hs[row][4 * cg + 3] = hv.w;
            float4 wv = *(const float4*)&W[(size_t)(o0 + row) * CCH + k0 + 4 * cg];
            Ws[row][4 * cg + 0] = wv.x; Ws[row][4 * cg + 1] = wv.y;
            Ws[row][4 * cg + 2] = wv.z; Ws[row][4 * cg + 3] = wv.w;
        }
        __syncthreads();
        #pragma unroll 16
        for (int k = 0; k < 32; k++) {
            float a[4], w[4];
            #pragma unroll
            for (int r = 0; r < 4; r++) a[r] = Hs[4 * ty + r][k];
            #pragma unroll
            for (int c = 0; c < 4; c++) w[c] = Ws[4 * tx + c][k];
            #pragma unroll
            for (int r = 0; r < 4; r++)
                #pragma unroll
                for (int c = 0; c < 4; c++) acc[r][c] += a[r] * w[c];
        }
    }
    float4 bs = *(const float4*)&bias[o0 + 4 * tx];
    float* Ob = g_QKV + (size_t)b * HWN * QKVC;
    #pragma unroll
    for (int r = 0; r < 4; r++) {
        float4 o4 = make_float4(acc[r][0] + bs.x, acc[r][1] + bs.y,
                                acc[r][2] + bs.z, acc[r][3] + bs.w);
        *(float4*)&Ob[(size_t)(p0 + 4 * ty + r) * QKVC + o0 + 4 * tx] = o4;
    }
}

// ---------------- 4) flash attention, BM=BN=64, fp32 -------------------------
__global__ void __launch_bounds__(256) attn_flash() {
    extern __shared__ float sm[];
    float (*Qs)[65] = (float(*)[65])(sm);
    float (*Ks)[65] = (float(*)[65])(sm + 64 * 65);
    float (*Vs)[65] = (float(*)[65])(sm + 2 * 64 * 65);
    float (*Ps)[65] = (float(*)[65])(sm + 3 * 64 * 65);

    int b = blockIdx.z, h = blockIdx.y, q0 = blockIdx.x * 64;
    int t = threadIdx.x, tx = t & 15, ty = t >> 4;
    const float* base = g_QKV + (size_t)b * HWN * QKVC + h * HDIM;

    // load Q tile (64 x 64)
    #pragma unroll
    for (int it = 0; it < 4; it++) {
        int lin = t + 256 * it;
        int row = lin >> 4, dg = lin & 15;
        float4 v = *(const float4*)&base[(size_t)(q0 + row) * QKVC + 4 * dg];
        Qs[row][4 * dg + 0] = v.x; Qs[row][4 * dg + 1] = v.y;
        Qs[row][4 * dg + 2] = v.z; Qs[row][4 * dg + 3] = v.w;
    }

    float acco[4][4];
    float mrun[4], lrun[4];
    #pragma unroll
    for (int r = 0; r < 4; r++) {
        mrun[r] = -1e30f; lrun[r] = 0.f;
        #pragma unroll
        for (int c = 0; c < 4; c++) acco[r][c] = 0.f;
    }

    const float scale = 0.125f;   // 1/sqrt(64)

    for (int j0 = 0; j0 < HWN; j0 += 64) {
        __syncthreads();   // previous PV done before K/V/P overwrite
        #pragma unroll
        for (int it = 0; it < 4; it++) {
            int lin = t + 256 * it;
            int row = lin >> 4, dg = lin & 15;
            float4 kv = *(const float4*)&base[(size_t)(j0 + row) * QKVC + 256 + 4 * dg];
            Ks[row][4 * dg + 0] = kv.x; Ks[row][4 * dg + 1] = kv.y;
            Ks[row][4 * dg + 2] = kv.z; Ks[row][4 * dg + 3] = kv.w;
            float4 vv = *(const float4*)&base[(size_t)(j0 + row) * QKVC + 512 + 4 * dg];
            Vs[row][4 * dg + 0] = vv.x; Vs[row][4 * dg + 1] = vv.y;
            Vs[row][4 * dg + 2] = vv.z; Vs[row][4 * dg + 3] = vv.w;
        }
        __syncthreads();

        // S = Q K^T  (4x4 per thread)
        float s[4][4];
        #pragma unroll
        for (int r = 0; r < 4; r++)
            #pragma unroll
            for (int c = 0; c < 4; c++) s[r][c] = 0.f;
        #pragma unroll 8
        for (int d = 0; d < 64; d++) {
            float qa[4], kb[4];
            #pragma unroll
            for (int r = 0; r < 4; r++) qa[r] = Qs[4 * ty + r][d];
            #pragma unroll
            for (int c = 0; c < 4; c++) kb[c] = Ks[4 * tx + c][d];
            #pragma unroll
            for (int r = 0; r < 4; r++)
                #pragma unroll
                for (int c = 0; c < 4; c++) s[r][c] += qa[r] * kb[c];
        }

        // online softmax per owned row
        #pragma unroll
        for (int r = 0; r < 4; r++) {
            float mx = s[r][0];
            #pragma unroll
            for (int c = 1; c < 4; c++) mx = fmaxf(mx, s[r][c]);
            mx *= scale;
            #pragma unroll
            for (int o = 1; o < 16; o <<= 1)
                mx = fmaxf(mx, __shfl_xor_sync(0xffffffffu, mx, o));
            float mnew = fmaxf(mrun[r], mx);
            float alpha = __expf(mrun[r] - mnew);
            float rs = 0.f;
            #pragma unroll
            for (int c = 0; c < 4; c++) {
                float pv = __expf(s[r][c] * scale - mnew);
                Ps[4 * ty + r][4 * tx + c] = pv;
                rs += pv;
            }
            #pragma unroll
            for (int o = 1; o < 16; o <<= 1)
                rs += __shfl_xor_sync(0xffffffffu, rs, o);
            lrun[r] = lrun[r] * alpha + rs;
            mrun[r] = mnew;
            #pragma unroll
            for (int c = 0; c < 4; c++) acco[r][c] *= alpha;
        }
        __syncthreads();

        // O += P V
        #pragma unroll 8
        for (int j = 0; j < 64; j++) {
            float pa[4], vb[4];
            #pragma unroll
            for (int r = 0; r < 4; r++) pa[r] = Ps[4 * ty + r][j];
            #pragma unroll
            for (int c = 0; c < 4; c++) vb[c] = Vs[j][4 * tx + c];
            #pragma unroll
            for (int r = 0; r < 4; r++)
                #pragma unroll
                for (int c = 0; c < 4; c++) acco[r][c] += pa[r] * vb[c];
        }
    }

    float* AO = g_AO + (size_t)b * HWN * CCH + h * HDIM;
    #pragma unroll
    for (int r = 0; r < 4; r++) {
        float inv = 1.f / lrun[r];
        float4 o4 = make_float4(acco[r][0] * inv, acco[r][1] * inv,
                                acco[r][2] * inv, acco[r][3] * inv);
        *(float4*)&AO[(size_t)(q0 + 4 * ty + r) * CCH + 4 * tx] = o4;
    }
}

// ---------------- 5) proj GEMM + bias + residual -----------------------------
// out[b][o][p] = x[b][o][p] + bias[o] + sum_c AO[b][p][c] * Wp[o][c]
__global__ void __launch_bounds__(256) proj_res(const float* __restrict__ x,
                                                const float* __restrict__ W,
                                                const float* __restrict__ bias,
                                                float* __restrict__ out) {
    __shared__ float Ws[64][33];
    __shared__ float As[64][33];
    int b  = blockIdx.z;
    int o0 = blockIdx.y * 64;
    int p0 = blockIdx.x * 64;
    int t  = threadIdx.x, tx = t & 15, ty = t >> 4;

    const float* Ab = g_AO + (size_t)(b * HWN + p0) * CCH;
    float acc[4][4];
    #pragma unroll
    for (int r = 0; r < 4; r++)
        #pragma unroll
        for (int c = 0; c < 4; c++) acc[r][c] = 0.f;

    for (int k0 = 0; k0 < CCH; k0 += 32) {
        __syncthreads();
        #pragma unroll
        for (int it = 0; it < 2; it++) {
            int lin = t + 256 * it;
            int row = lin >> 3, cg = lin & 7;
            float4 wv = *(const float4*)&W[(size_t)(o0 + row) * CCH + k0 + 4 * cg];
            Ws[row][4 * cg + 0] = wv.x; Ws[row][4 * cg + 1] = wv.y;
            Ws[row][4 * cg + 2] = wv.z; Ws[row][4 * cg + 3] = wv.w;
            float4 av = *(const float4*)&Ab[(size_t)row * CCH + k0 + 4 * cg];
            As[row][4 * cg + 0] = av.x; As[row][4 * cg + 1] = av.y;
            As[row][4 * cg + 2] = av.z; As[row][4 * cg + 3] = av.w;
        }
        __syncthreads();
        #pragma unroll 16
        for (int k = 0; k < 32; k++) {
            float w[4], a[4];
            #pragma unroll
            for (int r = 0; r < 4; r++) w[r] = Ws[4 * ty + r][k];
            #pragma unroll
            for (int c = 0; c < 4; c++) a[c] = As[4 * tx + c][k];
            #pragma unroll
            for (int r = 0; r < 4; r++)
                #pragma unroll
                for (int c = 0; c < 4; c++) acc[r][c] += w[r] * a[c];
        }
    }
    #pragma unroll
    for (int r = 0; r < 4; r++) {
        int o = o0 + 4 * ty + r;
        float bb = bias[o];
        size_t idx = ((size_t)(b * CCH + o)) * HWN + p0 + 4 * tx;
        float4 x4 = *(const float4*)&x[idx];
        float4 r4 = make_float4(x4.x + acc[r][0] + bb, x4.y + acc[r][1] + bb,
                                x4.z + acc[r][2] + bb, x4.w + acc[r][3] + bb);
        *(float4*)&out[idx] = r4;
    }
}

// ---------------- launcher ---------------------------------------------------
extern "C" void kernel_launch(void* const* d_in, const int* in_sizes, int n_in,
                              void* d_out, int out_size) {
    const float* x      = (const float*)d_in[0];
    const float* gamma  = (const float*)d_in[1];
    const float* beta   = (const float*)d_in[2];
    const float* w_qkv  = (const float*)d_in[3];
    const float* b_qkv  = (const float*)d_in[4];
    const float* w_proj = (const float*)d_in[5];
    const float* b_proj = (const float*)d_in[6];
    float* out = (float*)d_out;

    gn_stats<<<BATCH * NGRP, 1024>>>(x);
    gn_norm_t<<<dim3(HWN / 32, CCH / 32, BATCH), dim3(32, 8)>>>(x, gamma, beta);
    qkv_gemm<<<dim3(HWN / 64, QKVC / 64, BATCH), 256>>>(w_qkv, b_qkv);

    const int smem = 4 * 64 * 65 * (int)sizeof(float);   // 66,560 B
    cudaFuncSetAttribute(attn_flash, cudaFuncAttributeMaxDynamicSharedMemorySize, smem);
    attn_flash<<<dim3(HWN / 64, NHEAD, BATCH), 256, smem>>>();

    proj_res<<<dim3(HWN / 64, CCH / 64, BATCH), 256>>>(x, w_proj, b_proj, out);
}

// round 11
// speedup vs baseline: 1.1202x; 1.1167x over previous
#include <cuda_runtime.h>

#define BATCH 4
#define CCH   256
#define HWN   4096
#define NGRP  8
#define CPG   32
#define NHEAD 4
#define HDIM  64
#define QKVC  768

typedef unsigned long long u64;

// packed fp32x2 helpers (Blackwell FFMA2 path, PTX-only)
__device__ __forceinline__ u64 pk2(float lo, float hi) {
    u64 r; asm("mov.b64 %0,{%1,%2};" : "=l"(r) : "f"(lo), "f"(hi)); return r;
}
__device__ __forceinline__ void upk2(u64 v, float& lo, float& hi) {
    asm("mov.b64 {%0,%1},%2;" : "=f"(lo), "=f"(hi) : "l"(v));
}
__device__ __forceinline__ void ffma2(u64& d, u64 a, u64 b) {
    asm("fma.rn.f32x2 %0,%1,%2,%0;" : "+l"(d) : "l"(a), "l"(b));
}
__device__ __forceinline__ void fmul2(u64& d, u64 a) {
    asm("mul.rn.f32x2 %0,%0,%1;" : "+l"(d) : "l"(a));
}
__device__ __forceinline__ float hsum2(u64 v) {
    float lo, hi; upk2(v, lo, hi); return lo + hi;
}

// ---------------- scratch ----------------------------------------------------
__device__ float g_H  [BATCH * HWN * CCH];
__device__ float g_QKV[BATCH * HWN * QKVC];
__device__ float g_AO [BATCH * HWN * CCH];
__device__ float g_psum[BATCH * NGRP * 8];
__device__ float g_psq [BATCH * NGRP * 8];

// ---------------- 1) GroupNorm partial sums (8 blocks per group) -------------
__global__ void gn_part(const float* __restrict__ x) {
    int bg = blockIdx.x >> 3, slice = blockIdx.x & 7;
    const float4* p = (const float4*)(x + (size_t)bg * CPG * HWN) + slice * 4096;
    float s = 0.f, sq = 0.f;
    #pragma unroll 4
    for (int i = threadIdx.x; i < 4096; i += 256) {
        float4 v = p[i];
        s  += v.x + v.y + v.z + v.w;
        sq += v.x * v.x + v.y * v.y + v.z * v.z + v.w * v.w;
    }
    __shared__ float ss[8], sqs[8];
    #pragma unroll
    for (int o = 16; o; o >>= 1) {
        s  += __shfl_down_sync(0xffffffffu, s, o);
        sq += __shfl_down_sync(0xffffffffu, sq, o);
    }
    int w = threadIdx.x >> 5, l = threadIdx.x & 31;
    if (l == 0) { ss[w] = s; sqs[w] = sq; }
    __syncthreads();
    if (threadIdx.x == 0) {
        float ts = 0.f, tq = 0.f;
        #pragma unroll
        for (int i = 0; i < 8; i++) { ts += ss[i]; tq += sqs[i]; }
        g_psum[blockIdx.x] = ts;
        g_psq [blockIdx.x] = tq;
    }
}

// ---------------- 2) normalize + transpose [b,c,p] -> [b,p,c], vectorized ----
__global__ void __launch_bounds__(256) gn_norm_t(const float* __restrict__ x,
                                                 const float* __restrict__ gamma,
                                                 const float* __restrict__ beta) {
    __shared__ float tileT[128][36];   // [p_local][c_local]
    int b  = blockIdx.z;
    int c0 = blockIdx.y * 32;
    int p0 = blockIdx.x * 128;
    int tx = threadIdx.x, ty = threadIdx.y;  // (32, 8)

    int bg = b * NGRP + (c0 >> 5);
    float s = 0.f, sq = 0.f;
    #pragma unroll
    for (int i = 0; i < 8; i++) { s += g_psum[bg * 8 + i]; sq += g_psq[bg * 8 + i]; }
    const float invN = 1.f / (float)(CPG * HWN);
    float m = s * invN;
    float rstd = rsqrtf(sq * invN - m * m + 1e-5f);

    #pragma unroll
    for (int i = 0; i < 4; i++) {
        int c = c0 + ty + 8 * i;
        float ga = gamma[c] * rstd, be = beta[c] - m * gamma[c] * rstd;
        float4 v = *(const float4*)&x[((size_t)(b * CCH + c)) * HWN + p0 + 4 * tx];
        tileT[4 * tx + 0][ty + 8 * i] = v.x * ga + be;
        tileT[4 * tx + 1][ty + 8 * i] = v.y * ga + be;
        tileT[4 * tx + 2][ty + 8 * i] = v.z * ga + be;
        tileT[4 * tx + 3][ty + 8 * i] = v.w * ga + be;
    }
    __syncthreads();
    int t = ty * 32 + tx, cg = t & 7, pr = t >> 3;
    #pragma unroll
    for (int j = 0; j < 4; j++) {
        int pl = pr + 32 * j;
        float4 v = *(const float4*)&tileT[pl][4 * cg];
        *(float4*)&g_H[((size_t)(b * HWN + p0 + pl)) * CCH + c0 + 4 * cg] = v;
    }
}

// ---------------- 3) QKV GEMM (f32x2 packed over k) --------------------------
__global__ void __launch_bounds__(256) qkv_gemm(const float* __restrict__ W,
                                                const float* __restrict__ bias) {
    __shared__ float Hs[64][36];
    __shared__ float Ws[64][36];
    int b  = blockIdx.z;
    int o0 = blockIdx.y * 64;
    int p0 = blockIdx.x * 64;
    int t  = threadIdx.x, tx = t & 15, ty = t >> 4;

    const float* Hb = g_H + (size_t)(b * HWN + p0) * CCH;
    u64 acc[4][4];
    #pragma unroll
    for (int r = 0; r < 4; r++)
        #pragma unroll
        for (int c = 0; c < 4; c++) acc[r][c] = 0ull;

    for (int k0 = 0; k0 < CCH; k0 += 32) {
        __syncthreads();
        #pragma unroll
        for (int it = 0; it < 2; it++) {
            int lin = t + 256 * it;
            int row = lin >> 3, cg = lin & 7;
            *(float4*)&Hs[row][4 * cg] = *(const float4*)&Hb[(size_t)row * CCH + k0 + 4 * cg];
            *(float4*)&Ws[row][4 * cg] = *(const float4*)&W[(size_t)(o0 + row) * CCH + k0 + 4 * cg];
        }
        __syncthreads();
        #pragma unroll
        for (int k = 0; k < 32; k += 4) {
            u64 ap[4][2], wp[4][2];
            #pragma unroll
            for (int r = 0; r < 4; r++) {
                float4 v = *(const float4*)&Hs[4 * ty + r][k];
                ap[r][0] = pk2(v.x, v.y); ap[r][1] = pk2(v.z, v.w);
            }
            #pragma unroll
            for (int c = 0; c < 4; c++) {
                float4 v = *(const float4*)&Ws[tx + 16 * c][k];
                wp[c][0] = pk2(v.x, v.y); wp[c][1] = pk2(v.z, v.w);
            }
            #pragma unroll
            for (int r = 0; r < 4; r++)
                #pragma unroll
                for (int c = 0; c < 4; c++) {
                    ffma2(acc[r][c], ap[r][0], wp[c][0]);
                    ffma2(acc[r][c], ap[r][1], wp[c][1]);
                }
        }
    }
    float* Ob = g_QKV + (size_t)b * HWN * QKVC;
    #pragma unroll
    for (int c = 0; c < 4; c++) {
        int o = o0 + tx + 16 * c;
        float bb = bias[o];
        #pragma unroll
        for (int r = 0; r < 4; r++)
            Ob[(size_t)(p0 + 4 * ty + r) * QKVC + o] = hsum2(acc[r][c]) + bb;
    }
}

// ---------------- 4) flash attention, f32x2 packed ---------------------------
#define PAD 68
__global__ void __launch_bounds__(256) attn_flash() {
    extern __shared__ float sm[];
    float (*Qs)[PAD]  = (float(*)[PAD])(sm);
    float (*Ks)[PAD]  = (float(*)[PAD])(sm + 64 * PAD);
    float (*VsT)[PAD] = (float(*)[PAD])(sm + 2 * 64 * PAD);   // [d][j]
    float (*Ps)[PAD]  = (float(*)[PAD])(sm + 3 * 64 * PAD);

    int b = blockIdx.z, h = blockIdx.y, q0 = blockIdx.x * 64;
    int t = threadIdx.x, tx = t & 15, ty = t >> 4;
    const float* base = g_QKV + (size_t)b * HWN * QKVC + h * HDIM;

    #pragma unroll
    for (int it = 0; it < 4; it++) {
        int lin = t + 256 * it;
        int row = lin >> 4, dg = lin & 15;
        *(float4*)&Qs[row][4 * dg] = *(const float4*)&base[(size_t)(q0 + row) * QKVC + 4 * dg];
    }

    u64 o2[4][4];
    float mrun[4], lrun[4];
    #pragma unroll
    for (int r = 0; r < 4; r++) {
        mrun[r] = -1e30f; lrun[r] = 0.f;
        #pragma unroll
        for (int c = 0; c < 4; c++) o2[r][c] = 0ull;
    }
    const float scale = 0.125f;

    for (int j0 = 0; j0 < HWN; j0 += 64) {
        __syncthreads();
        #pragma unroll
        for (int it = 0; it < 4; it++) {
            int lin = t + 256 * it;
            int row = lin >> 4, dg = lin & 15;
            *(float4*)&Ks[row][4 * dg] =
                *(const float4*)&base[(size_t)(j0 + row) * QKVC + 256 + 4 * dg];
            float4 vv = *(const float4*)&base[(size_t)(j0 + row) * QKVC + 512 + 4 * dg];
            VsT[4 * dg + 0][row] = vv.x; VsT[4 * dg + 1][row] = vv.y;
            VsT[4 * dg + 2][row] = vv.z; VsT[4 * dg + 3][row] = vv.w;
        }
        __syncthreads();

        // S = Q K^T, packed over d
        u64 s2[4][4];
        #pragma unroll
        for (int r = 0; r < 4; r++)
            #pragma unroll
            for (int c = 0; c < 4; c++) s2[r][c] = 0ull;
        #pragma unroll 4
        for (int d = 0; d < 64; d += 4) {
            u64 qp[4][2], kp[4][2];
            #pragma unroll
            for (int r = 0; r < 4; r++) {
                float4 v = *(const float4*)&Qs[4 * ty + r][d];
                qp[r][0] = pk2(v.x, v.y); qp[r][1] = pk2(v.z, v.w);
            }
            #pragma unroll
            for (int c = 0; c < 4; c++) {
                float4 v = *(const float4*)&Ks[tx + 16 * c][d];
                kp[c][0] = pk2(v.x, v.y); kp[c][1] = pk2(v.z, v.w);
            }
            #pragma unroll
            for (int r = 0; r < 4; r++)
                #pragma unroll
                for (int c = 0; c < 4; c++) {
                    ffma2(s2[r][c], qp[r][0], kp[c][0]);
                    ffma2(s2[r][c], qp[r][1], kp[c][1]);
                }
        }

        // online softmax
        #pragma unroll
        for (int r = 0; r < 4; r++) {
            float s[4];
            #pragma unroll
            for (int c = 0; c < 4; c++) s[c] = hsum2(s2[r][c]);
            float mx = fmaxf(fmaxf(s[0], s[1]), fmaxf(s[2], s[3])) * scale;
            #pragma unroll
            for (int o = 1; o < 16; o <<= 1)
                mx = fmaxf(mx, __shfl_xor_sync(0xffffffffu, mx, o));
            float mnew = fmaxf(mrun[r], mx);
            float alpha = __expf(mrun[r] - mnew);
            float rs = 0.f;
            #pragma unroll
            for (int c = 0; c < 4; c++) {
                float pv = __expf(s[c] * scale - mnew);
                Ps[4 * ty + r][tx + 16 * c] = pv;
                rs += pv;
            }
            #pragma unroll
            for (int o = 1; o < 16; o <<= 1)
                rs += __shfl_xor_sync(0xffffffffu, rs, o);
            lrun[r] = lrun[r] * alpha + rs;
            mrun[r] = mnew;
            u64 a2 = pk2(alpha, alpha);
            #pragma unroll
            for (int c = 0; c < 4; c++) fmul2(o2[r][c], a2);
        }
        __syncthreads();

        // O += P V, packed over j
        #pragma unroll 4
        for (int j = 0; j < 64; j += 4) {
            u64 pp[4][2], vp[4][2];
            #pragma unroll
            for (int r = 0; r < 4; r++) {
                float4 v = *(const float4*)&Ps[4 * ty + r][j];
                pp[r][0] = pk2(v.x, v.y); pp[r][1] = pk2(v.z, v.w);
            }
            #pragma unroll
            for (int c = 0; c < 4; c++) {
                float4 v = *(const float4*)&VsT[tx + 16 * c][j];
                vp[c][0] = pk2(v.x, v.y); vp[c][1] = pk2(v.z, v.w);
            }
            #pragma unroll
            for (int r = 0; r < 4; r++)
                #pragma unroll
                for (int c = 0; c < 4; c++) {
                    ffma2(o2[r][c], pp[r][0], vp[c][0]);
                    ffma2(o2[r][c], pp[r][1], vp[c][1]);
                }
        }
    }

    float* AO = g_AO + (size_t)b * HWN * CCH + h * HDIM;
    #pragma unroll
    for (int r = 0; r < 4; r++) {
        float inv = 1.f / lrun[r];
        #pragma unroll
        for (int c = 0; c < 4; c++)
            AO[(size_t)(q0 + 4 * ty + r) * CCH + tx + 16 * c] = hsum2(o2[r][c]) * inv;
    }
}

// ---------------- 5) proj GEMM + bias + residual (f32x2) ---------------------
__global__ void __launch_bounds__(256) proj_res(const float* __restrict__ x,
                                                const float* __restrict__ W,
                                                const float* __restrict__ bias,
                                                float* __restrict__ out) {
    __shared__ float Ws[64][36];
    __shared__ float As[64][36];
    int b  = blockIdx.z;
    int o0 = blockIdx.y * 64;
    int p0 = blockIdx.x * 64;
    int t  = threadIdx.x, tx = t & 15, ty = t >> 4;

    const float* Ab = g_AO + (size_t)(b * HWN + p0) * CCH;
    u64 acc[4][4];
    #pragma unroll
    for (int r = 0; r < 4; r++)
        #pragma unroll
        for (int c = 0; c < 4; c++) acc[r][c] = 0ull;

    for (int k0 = 0; k0 < CCH; k0 += 32) {
        __syncthreads();
        #pragma unroll
        for (int it = 0; it < 2; it++) {
            int lin = t + 256 * it;
            int row = lin >> 3, cg = lin & 7;
            *(float4*)&Ws[row][4 * cg] = *(const float4*)&W[(size_t)(o0 + row) * CCH + k0 + 4 * cg];
            *(float4*)&As[row][4 * cg] = *(const float4*)&Ab[(size_t)row * CCH + k0 + 4 * cg];
        }
        __syncthreads();
        #pragma unroll
        for (int k = 0; k < 32; k += 4) {
            u64 wp[4][2], ap[4][2];
            #pragma unroll
            for (int r = 0; r < 4; r++) {
                float4 v = *(const float4*)&Ws[4 * ty + r][k];
                wp[r][0] = pk2(v.x, v.y); wp[r][1] = pk2(v.z, v.w);
            }
            #pragma unroll
            for (int c = 0; c < 4; c++) {
                float4 v = *(const float4*)&As[tx + 16 * c][k];
                ap[c][0] = pk2(v.x, v.y); ap[c][1] = pk2(v.z, v.w);
            }
            #pragma unroll
            for (int r = 0; r < 4; r++)
                #pragma unroll
                for (int c = 0; c < 4; c++) {
                    ffma2(acc[r][c], wp[r][0], ap[c][0]);
                    ffma2(acc[r][c], wp[r][1], ap[c][1]);
                }
        }
    }
    #pragma unroll
    for (int r = 0; r < 4; r++) {
        int o = o0 + 4 * ty + r;
        float bb = bias[o];
        #pragma unroll
        for (int c = 0; c < 4; c++) {
            size_t idx = ((size_t)(b * CCH + o)) * HWN + p0 + tx + 16 * c;
            out[idx] = x[idx] + hsum2(acc[r][c]) + bb;
        }
    }
}

// ---------------- launcher ---------------------------------------------------
extern "C" void kernel_launch(void* const* d_in, const int* in_sizes, int n_in,
                              void* d_out, int out_size) {
    const float* x      = (const float*)d_in[0];
    const float* gamma  = (const float*)d_in[1];
    const float* beta   = (const float*)d_in[2];
    const float* w_qkv  = (const float*)d_in[3];
    const float* b_qkv  = (const float*)d_in[4];
    const float* w_proj = (const float*)d_in[5];
    const float* b_proj = (const float*)d_in[6];
    float* out = (float*)d_out;

    gn_part<<<BATCH * NGRP * 8, 256>>>(x);
    gn_norm_t<<<dim3(HWN / 128, CCH / 32, BATCH), dim3(32, 8)>>>(x, gamma, beta);
    qkv_gemm<<<dim3(HWN / 64, QKVC / 64, BATCH), 256>>>(w_qkv, b_qkv);

    const int smem = 4 * 64 * PAD * (int)sizeof(float);   // 69,632 B
    cudaFuncSetAttribute(attn_flash, cudaFuncAttributeMaxDynamicSharedMemorySize, smem);
    attn_flash<<<dim3(HWN / 64, NHEAD, BATCH), 256, smem>>>();

    proj_res<<<dim3(HWN / 64, CCH / 64, BATCH), 256>>>(x, w_proj, b_proj, out);
}